// round 5
// baseline (speedup 1.0000x reference)
#include <cuda_runtime.h>
#include <cstdint>

// CharRNN on GB300 (sm_103a), round 5: occupancy over reuse.
// 128 blocks x 640 threads (20 warps = 5/SMSP, up from 3).
// Each layer l has TWO warps: wid = 2l + pip, pip = row-half (rows 0-3 / 4-7).
// Lane owns ONE neuron (64 weight regs) -> ~95 regs/thread -> 20 warps fit RF.
// The four layer-8/9 warps double as embedding producers (2 rows each),
// arriving at bar 1 FIRST each tick (no barrier cycle; 1-hop sx visibility
// to layer 0 with 9-tick slack both RAW and WAR).
// 4 steps/tick, depth-8 layer rings, depth-80 embedding ring, PREF=40.

#define NBLK  128
#define NTHR  640
#define ROWS  8
#define TT    1024
#define LL    10
#define HID   32
#define VOC   256
#define LST   36
#define RL    (ROWS*LST)
#define DEPTH 8
#define XDEP  80
#define PREF  40
#define NTICK 265

typedef unsigned long long ull;

__device__ __forceinline__ void ffma2(ull &d, ull a, ull b) {
    asm("fma.rn.f32x2 %0, %1, %2, %0;" : "+l"(d) : "l"(a), "l"(b));
}
__device__ __forceinline__ float f2red(ull a) {
    float lo, hi;
    asm("mov.b64 {%0, %1}, %2;" : "=f"(lo), "=f"(hi) : "l"(a));
    return lo + hi;
}
__device__ __forceinline__ float tanh_fast(float x) {
    float e = __expf(2.0f * x);
    return 1.0f - __fdividef(2.0f, e + 1.0f);
}
__device__ __forceinline__ void nbar(int id, int cnt) {
    asm volatile("bar.sync %0, %1;" :: "r"(id), "r"(cnt) : "memory");
}

__global__ void __launch_bounds__(NTHR, 1)
charrnn_kernel(const int*   __restrict__ x,
               const float* __restrict__ emb,
               const float* __restrict__ W_ih,
               const float* __restrict__ W_hh,
               const float* __restrict__ b_ih,
               const float* __restrict__ b_hh,
               const float* __restrict__ W_fc,
               const float* __restrict__ b_fc,
               float*       __restrict__ out)
{
    extern __shared__ float smem[];
    float* shl = smem;                    // [LL][DEPTH][ROWS][LST]
    float* sx  = smem + LL * DEPTH * RL;  // [XDEP][ROWS][LST]

    const int tid  = threadIdx.x;
    const int wid  = tid >> 5;
    const int lane = tid & 31;
    const int row0 = blockIdx.x * ROWS;

    for (int i = tid; i < LL * DEPTH * RL; i += NTHR) shl[i] = 0.0f;

    const int  l     = wid >> 1;          // layer 0..9
    const int  rb    = (wid & 1) * 4;     // row half
    const bool isEmb = (l >= 8);          // 4 producer warps
    const int  er0   = (wid - 16) * 2;    // producer-owned rows
    const int  er1   = er0 + 1;

    // ---- weights: lane = output neuron, f32x2-packed ----
    ull wih[16], whh[16];
    {
        const ulonglong2* p;
        p = (const ulonglong2*)(W_ih + (l * HID + lane) * HID);
        #pragma unroll
        for (int q = 0; q < 8; ++q) { ulonglong2 v = p[q]; wih[2*q] = v.x; wih[2*q+1] = v.y; }
        p = (const ulonglong2*)(W_hh + (l * HID + lane) * HID);
        #pragma unroll
        for (int q = 0; q < 8; ++q) { ulonglong2 v = p[q]; whh[2*q] = v.x; whh[2*q+1] = v.y; }
    }
    const float bias = __ldg(&b_ih[l * HID + lane]) + __ldg(&b_hh[l * HID + lane]);

    // ---- prefill sx steps [0, PREF) ----
    for (int i = wid; i < PREF * ROWS; i += 20) {
        const int t = i >> 3, r = i & 7;
        const int idx = __ldg(&x[(row0 + r) * TT + t]);
        sx[t * RL + r * LST + lane] = __ldg(&emb[idx * HID + lane]);
    }
    __syncthreads();

    const float* base_in  = (l == 0) ? sx : (shl + (l - 1) * DEPTH * RL);
    float*       base_own = shl + l * DEPTH * RL;
    int xs = 0;      // layer-0 sx read cursor
    int ws = PREF;   // producer sx write cursor

    for (int v = 0; v < NTICK; ++v) {
        float g[8];
        bool doemb = false;

        if (isEmb) {
            // producers arrive bar 1 FIRST: publishes last tick's sx writes
            // directly to layer 0 and breaks any barrier cycle.
            nbar(1, 192);
            const int te = 4 * v + PREF;
            doemb = (te < TT);
            if (doemb) {
                const int4 iA = *(const int4*)(x + (row0 + er0) * TT + te);
                const int4 iB = *(const int4*)(x + (row0 + er1) * TT + te);
                g[0] = __ldg(&emb[iA.x * HID + lane]);
                g[1] = __ldg(&emb[iA.y * HID + lane]);
                g[2] = __ldg(&emb[iA.z * HID + lane]);
                g[3] = __ldg(&emb[iA.w * HID + lane]);
                g[4] = __ldg(&emb[iB.x * HID + lane]);
                g[5] = __ldg(&emb[iB.y * HID + lane]);
                g[6] = __ldg(&emb[iB.z * HID + lane]);
                g[7] = __ldg(&emb[iB.w * HID + lane]);
            }
        }

        // upstream rendezvous
        if (l == 0) nbar(1, 192);
        else        nbar(l + 1, 128);

        const int t0 = 4 * (v - l);
        if (t0 >= 0 && t0 < TT) {
            #pragma unroll
            for (int st = 0; st < 4; ++st) {
                const int t = t0 + st;
                const float* inb = (l == 0) ? (sx + (xs + st) * RL)
                                            : (base_in + (t & (DEPTH-1)) * RL);
                const float* hb  = base_own + ((t - 1) & (DEPTH-1)) * RL;
                float*       ob  = base_own + (t & (DEPTH-1)) * RL;

                ull a0 = 0ull, a1 = 0ull, a2 = 0ull, a3 = 0ull;
                #pragma unroll
                for (int q = 0; q < 8; ++q) {
                    ulonglong2 v0 = *(const ulonglong2*)(inb + (rb+0) * LST + q * 4);
                    ulonglong2 v1 = *(const ulonglong2*)(inb + (rb+1) * LST + q * 4);
                    ulonglong2 v2 = *(const ulonglong2*)(inb + (rb+2) * LST + q * 4);
                    ulonglong2 v3 = *(const ulonglong2*)(inb + (rb+3) * LST + q * 4);
                    ffma2(a0, wih[2*q], v0.x); ffma2(a0, wih[2*q+1], v0.y);
                    ffma2(a1, wih[2*q], v1.x); ffma2(a1, wih[2*q+1], v1.y);
                    ffma2(a2, wih[2*q], v2.x); ffma2(a2, wih[2*q+1], v2.y);
                    ffma2(a3, wih[2*q], v3.x); ffma2(a3, wih[2*q+1], v3.y);
                }
                #pragma unroll
                for (int q = 0; q < 8; ++q) {
                    ulonglong2 v0 = *(const ulonglong2*)(hb + (rb+0) * LST + q * 4);
                    ulonglong2 v1 = *(const ulonglong2*)(hb + (rb+1) * LST + q * 4);
                    ulonglong2 v2 = *(const ulonglong2*)(hb + (rb+2) * LST + q * 4);
                    ulonglong2 v3 = *(const ulonglong2*)(hb + (rb+3) * LST + q * 4);
                    ffma2(a0, whh[2*q], v0.x); ffma2(a0, whh[2*q+1], v0.y);
                    ffma2(a1, whh[2*q], v1.x); ffma2(a1, whh[2*q+1], v1.y);
                    ffma2(a2, whh[2*q], v2.x); ffma2(a2, whh[2*q+1], v2.y);
                    ffma2(a3, whh[2*q], v3.x); ffma2(a3, whh[2*q+1], v3.y);
                }
                ob[(rb+0) * LST + lane] = tanh_fast(f2red(a0) + bias);
                ob[(rb+1) * LST + lane] = tanh_fast(f2red(a1) + bias);
                ob[(rb+2) * LST + lane] = tanh_fast(f2red(a2) + bias);
                ob[(rb+3) * LST + lane] = tanh_fast(f2red(a3) + bias);
                __syncwarp();
            }
            if (l == 0) { xs += 4; if (xs == XDEP) xs = 0; }
        }

        // producer: publish gathered embeddings (visible via next tick's bar 1)
        if (doemb) {
            #pragma unroll
            for (int s = 0; s < 4; ++s) {
                sx[(ws + s) * RL + er0 * LST + lane] = g[s];
                sx[(ws + s) * RL + er1 * LST + lane] = g[4 + s];
            }
            ws += 4; if (ws == XDEP) ws = 0;
        }

        // downstream rendezvous
        if (l < 9) nbar(l + 2, 128);
    }

    __syncthreads();

    // ---- final FC: out = h9(1023) @ W_fc^T + b_fc ; slot 1023&7 = 7 ----
    const float* h9 = shl + ((LL - 1) * DEPTH + 7) * RL;
    for (int i = tid; i < ROWS * VOC; i += NTHR) {
        const int r = i >> 8;
        const int vv = i & (VOC - 1);
        const float4* w  = (const float4*)(W_fc + vv * HID);
        const float*  hr = h9 + r * LST;
        float sum = __ldg(&b_fc[vv]);
        #pragma unroll
        for (int q = 0; q < 8; ++q) {
            float4 a = w[q];
            sum += a.x * hr[q*4+0] + a.y * hr[q*4+1] + a.z * hr[q*4+2] + a.w * hr[q*4+3];
        }
        out[(row0 + r) * VOC + vv] = sum;
    }
}

extern "C" void kernel_launch(void* const* d_in, const int* in_sizes, int n_in,
                              void* d_out, int out_size)
{
    const int*   x    = (const int*)  d_in[0];
    const float* emb  = (const float*)d_in[1];
    const float* W_ih = (const float*)d_in[2];
    const float* W_hh = (const float*)d_in[3];
    const float* b_ih = (const float*)d_in[4];
    const float* b_hh = (const float*)d_in[5];
    const float* W_fc = (const float*)d_in[6];
    const float* b_fc = (const float*)d_in[7];
    float* out = (float*)d_out;

    const int shbytes = (LL * DEPTH + XDEP) * RL * (int)sizeof(float);
    cudaFuncSetAttribute(charrnn_kernel,
                         cudaFuncAttributeMaxDynamicSharedMemorySize, shbytes);
    charrnn_kernel<<<NBLK, NTHR, shbytes>>>(x, emb, W_ih, W_hh, b_ih, b_hh,
                                            W_fc, b_fc, out);
}

// round 6
// speedup vs baseline: 6.1558x; 6.1558x over previous
#include <cuda_runtime.h>
#include <cstdint>

// CharRNN on GB300 (sm_103a), round 6 = round 5 layout + round 3 barrier phase.
// 128 blocks x 640 threads (20 warps = 5/SMSP).
// Each layer l has TWO warps (row halves 0-3 / 4-7), lane owns ONE neuron.
// ALL barriers at END of tick: layers compute concurrently as a wavefront
// (layer l at tick v does t = 4(v-l)..+3), pairwise bar(l+1) with upstream,
// bar(l+2) with downstream orders tick-(v-1) writes before tick-v reads.
// Layer-8/9 warps double as embedding producers (2 rows each, PREF=40 ahead);
// bar 1 (layer-0 warps + producers, 192 thr) gives 1-tick sx visibility.

#define NBLK  128
#define NTHR  640
#define ROWS  8
#define TT    1024
#define LL    10
#define HID   32
#define VOC   256
#define LST   36
#define RL    (ROWS*LST)
#define DEPTH 8
#define XDEP  80
#define PREF  40
#define NTICK 265

typedef unsigned long long ull;

__device__ __forceinline__ void ffma2(ull &d, ull a, ull b) {
    asm("fma.rn.f32x2 %0, %1, %2, %0;" : "+l"(d) : "l"(a), "l"(b));
}
__device__ __forceinline__ float f2red(ull a) {
    float lo, hi;
    asm("mov.b64 {%0, %1}, %2;" : "=f"(lo), "=f"(hi) : "l"(a));
    return lo + hi;
}
__device__ __forceinline__ float tanh_fast(float x) {
    float e = __expf(2.0f * x);
    return 1.0f - __fdividef(2.0f, e + 1.0f);
}
__device__ __forceinline__ void nbar(int id, int cnt) {
    asm volatile("bar.sync %0, %1;" :: "r"(id), "r"(cnt) : "memory");
}

__global__ void __launch_bounds__(NTHR, 1)
charrnn_kernel(const int*   __restrict__ x,
               const float* __restrict__ emb,
               const float* __restrict__ W_ih,
               const float* __restrict__ W_hh,
               const float* __restrict__ b_ih,
               const float* __restrict__ b_hh,
               const float* __restrict__ W_fc,
               const float* __restrict__ b_fc,
               float*       __restrict__ out)
{
    extern __shared__ float smem[];
    float* shl = smem;                    // [LL][DEPTH][ROWS][LST]
    float* sx  = smem + LL * DEPTH * RL;  // [XDEP][ROWS][LST]

    const int tid  = threadIdx.x;
    const int wid  = tid >> 5;
    const int lane = tid & 31;
    const int row0 = blockIdx.x * ROWS;

    for (int i = tid; i < LL * DEPTH * RL; i += NTHR) shl[i] = 0.0f;

    const int  l     = wid >> 1;          // layer 0..9
    const int  rb    = (wid & 1) * 4;     // row half
    const bool isEmb = (l >= 8);          // 4 producer warps
    const int  er0   = (wid - 16) * 2;    // producer-owned rows
    const int  er1   = er0 + 1;

    ull wih[16], whh[16];
    {
        const ulonglong2* p;
        p = (const ulonglong2*)(W_ih + (l * HID + lane) * HID);
        #pragma unroll
        for (int q = 0; q < 8; ++q) { ulonglong2 v = p[q]; wih[2*q] = v.x; wih[2*q+1] = v.y; }
        p = (const ulonglong2*)(W_hh + (l * HID + lane) * HID);
        #pragma unroll
        for (int q = 0; q < 8; ++q) { ulonglong2 v = p[q]; whh[2*q] = v.x; whh[2*q+1] = v.y; }
    }
    const float bias = __ldg(&b_ih[l * HID + lane]) + __ldg(&b_hh[l * HID + lane]);

    for (int i = wid; i < PREF * ROWS; i += 20) {
        const int t = i >> 3, r = i & 7;
        const int idx = __ldg(&x[(row0 + r) * TT + t]);
        sx[t * RL + r * LST + lane] = __ldg(&emb[idx * HID + lane]);
    }
    __syncthreads();

    const float* base_in  = (l == 0) ? sx : (shl + (l - 1) * DEPTH * RL);
    float*       base_own = shl + l * DEPTH * RL;
    int xs = 0;      // layer-0 sx read cursor
    int ws = PREF;   // producer sx write cursor

    for (int v = 0; v < NTICK; ++v) {
        // ---- producer gather (independent of this tick's compute) ----
        float g[8];
        bool doemb = false;
        if (isEmb) {
            const int te = 4 * v + PREF;
            doemb = (te < TT);
            if (doemb) {
                const int4 iA = *(const int4*)(x + (row0 + er0) * TT + te);
                const int4 iB = *(const int4*)(x + (row0 + er1) * TT + te);
                g[0] = __ldg(&emb[iA.x * HID + lane]);
                g[1] = __ldg(&emb[iA.y * HID + lane]);
                g[2] = __ldg(&emb[iA.z * HID + lane]);
                g[3] = __ldg(&emb[iA.w * HID + lane]);
                g[4] = __ldg(&emb[iB.x * HID + lane]);
                g[5] = __ldg(&emb[iB.y * HID + lane]);
                g[6] = __ldg(&emb[iB.z * HID + lane]);
                g[7] = __ldg(&emb[iB.w * HID + lane]);
            }
        }

        // ---- compute phase: all layers concurrent (wavefront) ----
        const int t0 = 4 * (v - l);
        if (t0 >= 0 && t0 < TT) {
            #pragma unroll
            for (int st = 0; st < 4; ++st) {
                const int t = t0 + st;
                const float* inb = (l == 0) ? (sx + (xs + st) * RL)
                                            : (base_in + (t & (DEPTH-1)) * RL);
                const float* hb  = base_own + ((t - 1) & (DEPTH-1)) * RL;
                float*       ob  = base_own + (t & (DEPTH-1)) * RL;

                ull a0 = 0ull, a1 = 0ull, a2 = 0ull, a3 = 0ull;
                #pragma unroll
                for (int q = 0; q < 8; ++q) {
                    ulonglong2 v0 = *(const ulonglong2*)(inb + (rb+0) * LST + q * 4);
                    ulonglong2 v1 = *(const ulonglong2*)(inb + (rb+1) * LST + q * 4);
                    ulonglong2 v2 = *(const ulonglong2*)(inb + (rb+2) * LST + q * 4);
                    ulonglong2 v3 = *(const ulonglong2*)(inb + (rb+3) * LST + q * 4);
                    ffma2(a0, wih[2*q], v0.x); ffma2(a0, wih[2*q+1], v0.y);
                    ffma2(a1, wih[2*q], v1.x); ffma2(a1, wih[2*q+1], v1.y);
                    ffma2(a2, wih[2*q], v2.x); ffma2(a2, wih[2*q+1], v2.y);
                    ffma2(a3, wih[2*q], v3.x); ffma2(a3, wih[2*q+1], v3.y);
                }
                #pragma unroll
                for (int q = 0; q < 8; ++q) {
                    ulonglong2 v0 = *(const ulonglong2*)(hb + (rb+0) * LST + q * 4);
                    ulonglong2 v1 = *(const ulonglong2*)(hb + (rb+1) * LST + q * 4);
                    ulonglong2 v2 = *(const ulonglong2*)(hb + (rb+2) * LST + q * 4);
                    ulonglong2 v3 = *(const ulonglong2*)(hb + (rb+3) * LST + q * 4);
                    ffma2(a0, whh[2*q], v0.x); ffma2(a0, whh[2*q+1], v0.y);
                    ffma2(a1, whh[2*q], v1.x); ffma2(a1, whh[2*q+1], v1.y);
                    ffma2(a2, whh[2*q], v2.x); ffma2(a2, whh[2*q+1], v2.y);
                    ffma2(a3, whh[2*q], v3.x); ffma2(a3, whh[2*q+1], v3.y);
                }
                ob[(rb+0) * LST + lane] = tanh_fast(f2red(a0) + bias);
                ob[(rb+1) * LST + lane] = tanh_fast(f2red(a1) + bias);
                ob[(rb+2) * LST + lane] = tanh_fast(f2red(a2) + bias);
                ob[(rb+3) * LST + lane] = tanh_fast(f2red(a3) + bias);
                __syncwarp();
            }
            if (l == 0) { xs += 4; if (xs == XDEP) xs = 0; }
        }

        // ---- producer publish ----
        if (doemb) {
            #pragma unroll
            for (int s = 0; s < 4; ++s) {
                sx[(ws + s) * RL + er0 * LST + lane] = g[s];
                sx[(ws + s) * RL + er1 * LST + lane] = g[4 + s];
            }
            ws += 4; if (ws == XDEP) ws = 0;
        }

        // ---- rendezvous phase (END of tick only) ----
        if (l == 0 || isEmb) nbar(1, 192);   // sx handoff: layer 0 + producers
        if (l >= 1) nbar(l + 1, 128);        // with upstream layer
        if (l < 9)  nbar(l + 2, 128);        // with downstream layer
    }

    __syncthreads();

    // ---- final FC ----
    const float* h9 = shl + ((LL - 1) * DEPTH + 7) * RL;
    for (int i = tid; i < ROWS * VOC; i += NTHR) {
        const int r = i >> 8;
        const int vv = i & (VOC - 1);
        const float4* w  = (const float4*)(W_fc + vv * HID);
        const float*  hr = h9 + r * LST;
        float sum = __ldg(&b_fc[vv]);
        #pragma unroll
        for (int q = 0; q < 8; ++q) {
            float4 a = w[q];
            sum += a.x * hr[q*4+0] + a.y * hr[q*4+1] + a.z * hr[q*4+2] + a.w * hr[q*4+3];
        }
        out[(row0 + r) * VOC + vv] = sum;
    }
}

extern "C" void kernel_launch(void* const* d_in, const int* in_sizes, int n_in,
                              void* d_out, int out_size)
{
    const int*   x    = (const int*)  d_in[0];
    const float* emb  = (const float*)d_in[1];
    const float* W_ih = (const float*)d_in[2];
    const float* W_hh = (const float*)d_in[3];
    const float* b_ih = (const float*)d_in[4];
    const float* b_hh = (const float*)d_in[5];
    const float* W_fc = (const float*)d_in[6];
    const float* b_fc = (const float*)d_in[7];
    float* out = (float*)d_out;

    const int shbytes = (LL * DEPTH + XDEP) * RL * (int)sizeof(float);
    cudaFuncSetAttribute(charrnn_kernel,
                         cudaFuncAttributeMaxDynamicSharedMemorySize, shbytes);
    charrnn_kernel<<<NBLK, NTHR, shbytes>>>(x, emb, W_ih, W_hh, b_ih, b_hh,
                                            W_fc, b_fc, out);
}

// round 7
// speedup vs baseline: 6.7471x; 1.0961x over previous
#include <cuda_runtime.h>
#include <cstdint>

// CharRNN on GB300 (sm_103a), round 7: GEMM/REC warp specialization.
// 128 blocks x 640 threads (20 warps). Block owns 8 batch rows.
// 20 pipeline stages (2 per layer): stage 2l = GEMM_l (z = Wih.x + bias,
// no serial dep), stage 2l+1 = REC_l (h = tanh(z + Whh.h), the recurrence).
// Warps 0..9 = REC layers 0..9; warps 10..19 = GEMM layers 0..9
// (interleaves roles across SMSPs: each SMSP gets ~2-3 REC + 2-3 GEMM).
// 4 steps/tick, depth-8 rings for h and z, one __syncthreads per tick.
// GEMM_0 gathers embeddings itself (LDG, latency-tolerant) via a tiny
// per-tick smem stage. Lane owns ONE neuron; weights 32 regs per warp role.

#define NBLK  128
#define NTHR  640
#define ROWS  8
#define TT    1024
#define LL    10
#define HID   32
#define VOC   256
#define LST   36
#define RL    (ROWS*LST)
#define DEPTH 8
#define NTICK 275            // last REC9 tick: 4(v-19)+3=1023 -> v=274

typedef unsigned long long ull;

__device__ __forceinline__ void ffma2(ull &d, ull a, ull b) {
    asm("fma.rn.f32x2 %0, %1, %2, %0;" : "+l"(d) : "l"(a), "l"(b));
}
__device__ __forceinline__ float f2red(ull a) {
    float lo, hi;
    asm("mov.b64 {%0, %1}, %2;" : "=f"(lo), "=f"(hi) : "l"(a));
    return lo + hi;
}
__device__ __forceinline__ float tanh_fast(float x) {
    float e = __expf(2.0f * x);
    return 1.0f - __fdividef(2.0f, e + 1.0f);
}

__global__ void __launch_bounds__(NTHR, 1)
charrnn_kernel(const int*   __restrict__ x,
               const float* __restrict__ emb,
               const float* __restrict__ W_ih,
               const float* __restrict__ W_hh,
               const float* __restrict__ b_ih,
               const float* __restrict__ b_hh,
               const float* __restrict__ W_fc,
               const float* __restrict__ b_fc,
               float*       __restrict__ out)
{
    extern __shared__ float smem[];
    float* sh  = smem;                        // h rings [LL][DEPTH][ROWS][LST]
    float* sz  = smem + LL * DEPTH * RL;      // z rings [LL][DEPTH][ROWS][LST]
    float* sxs = sz   + LL * DEPTH * RL;      // GEMM_0 stage [4][ROWS][LST]

    const int tid  = threadIdx.x;
    const int wid  = tid >> 5;
    const int lane = tid & 31;
    const int row0 = blockIdx.x * ROWS;

    // zero h rings (h(-1)=0 read from slot 7 at t=0)
    for (int i = tid; i < LL * DEPTH * RL; i += NTHR) sh[i] = 0.0f;

    const bool isRec = (wid < 10);
    const int  l     = isRec ? wid : (wid - 10);

    // role weights: REC -> Whh row, GEMM -> Wih row (32 regs each)
    ull w[16];
    {
        const float* wsrc = isRec ? (W_hh + (l * HID + lane) * HID)
                                  : (W_ih + (l * HID + lane) * HID);
        const ulonglong2* p = (const ulonglong2*)wsrc;
        #pragma unroll
        for (int q = 0; q < 8; ++q) { ulonglong2 v = p[q]; w[2*q] = v.x; w[2*q+1] = v.y; }
    }
    const float bias = isRec ? 0.0f
                             : (__ldg(&b_ih[l * HID + lane]) + __ldg(&b_hh[l * HID + lane]));

    __syncthreads();

    float*       hown = sh + l * DEPTH * RL;
    const float* hup  = (l > 0) ? (sh + (l - 1) * DEPTH * RL) : sxs;
    float*       zl   = sz + l * DEPTH * RL;

    for (int v = 0; v < NTICK; ++v) {
        if (!isRec) {
            // ================= GEMM stage 2l: z(t) for t = 4(v-2l).. =================
            const int t0 = 4 * (v - 2 * l);
            if (t0 >= 0 && t0 < TT) {
                if (l == 0) {
                    // embedding gather into per-tick stage (own-warp only)
                    #pragma unroll
                    for (int r = 0; r < ROWS; ++r) {
                        const int4 xi = *(const int4*)(x + (row0 + r) * TT + t0);
                        sxs[0 * RL + r * LST + lane] = __ldg(&emb[xi.x * HID + lane]);
                        sxs[1 * RL + r * LST + lane] = __ldg(&emb[xi.y * HID + lane]);
                        sxs[2 * RL + r * LST + lane] = __ldg(&emb[xi.z * HID + lane]);
                        sxs[3 * RL + r * LST + lane] = __ldg(&emb[xi.w * HID + lane]);
                    }
                    __syncwarp();
                }
                #pragma unroll
                for (int st = 0; st < 4; ++st) {
                    const int t = t0 + st;
                    const float* inb = (l == 0) ? (sxs + st * RL)
                                                : (hup + (t & (DEPTH-1)) * RL);
                    float* zo = zl + (t & (DEPTH-1)) * RL;

                    #pragma unroll
                    for (int r = 0; r < ROWS; r += 2) {
                        ull a0 = 0ull, a1 = 0ull;
                        #pragma unroll
                        for (int q = 0; q < 8; ++q) {
                            ulonglong2 v0 = *(const ulonglong2*)(inb + (r+0) * LST + q * 4);
                            ulonglong2 v1 = *(const ulonglong2*)(inb + (r+1) * LST + q * 4);
                            ffma2(a0, w[2*q], v0.x); ffma2(a0, w[2*q+1], v0.y);
                            ffma2(a1, w[2*q], v1.x); ffma2(a1, w[2*q+1], v1.y);
                        }
                        zo[(r+0) * LST + lane] = f2red(a0) + bias;
                        zo[(r+1) * LST + lane] = f2red(a1) + bias;
                    }
                }
            }
        } else {
            // ================= REC stage 2l+1: h(t) for t = 4(v-2l-1).. =================
            const int t0 = 4 * (v - 2 * l - 1);
            if (t0 >= 0 && t0 < TT) {
                #pragma unroll
                for (int st = 0; st < 4; ++st) {
                    const int t = t0 + st;
                    const float* hb   = hown + ((t - 1) & (DEPTH-1)) * RL;
                    const float* zrow = zl   + (t & (DEPTH-1)) * RL;
                    float*       ob   = hown + (t & (DEPTH-1)) * RL;

                    // z values first (independent of h)
                    float zv[ROWS];
                    #pragma unroll
                    for (int r = 0; r < ROWS; ++r) zv[r] = zrow[r * LST + lane];

                    ull a[ROWS];
                    #pragma unroll
                    for (int r = 0; r < ROWS; ++r) a[r] = 0ull;
                    #pragma unroll
                    for (int r = 0; r < ROWS; r += 2) {
                        #pragma unroll
                        for (int q = 0; q < 8; ++q) {
                            ulonglong2 v0 = *(const ulonglong2*)(hb + (r+0) * LST + q * 4);
                            ulonglong2 v1 = *(const ulonglong2*)(hb + (r+1) * LST + q * 4);
                            ffma2(a[r+0], w[2*q], v0.x); ffma2(a[r+0], w[2*q+1], v0.y);
                            ffma2(a[r+1], w[2*q], v1.x); ffma2(a[r+1], w[2*q+1], v1.y);
                        }
                    }
                    #pragma unroll
                    for (int r = 0; r < ROWS; ++r)
                        ob[r * LST + lane] = tanh_fast(f2red(a[r]) + zv[r]);
                    __syncwarp();   // own next step reads all lanes' h
                }
            }
        }
        __syncthreads();   // tick rendezvous: publishes h and z cross-warp
    }

    // ---- final FC: out = h9(1023) @ W_fc^T + b_fc ; slot 1023&7 = 7 ----
    const float* h9 = sh + ((LL - 1) * DEPTH + 7) * RL;
    for (int i = tid; i < ROWS * VOC; i += NTHR) {
        const int r  = i >> 8;
        const int vv = i & (VOC - 1);
        const float4* wfc = (const float4*)(W_fc + vv * HID);
        const float*  hr  = h9 + r * LST;
        float sum = __ldg(&b_fc[vv]);
        #pragma unroll
        for (int q = 0; q < 8; ++q) {
            float4 aw = wfc[q];
            sum += aw.x * hr[q*4+0] + aw.y * hr[q*4+1] + aw.z * hr[q*4+2] + aw.w * hr[q*4+3];
        }
        out[(row0 + r) * VOC + vv] = sum;
    }
}

extern "C" void kernel_launch(void* const* d_in, const int* in_sizes, int n_in,
                              void* d_out, int out_size)
{
    const int*   x    = (const int*)  d_in[0];
    const float* emb  = (const float*)d_in[1];
    const float* W_ih = (const float*)d_in[2];
    const float* W_hh = (const float*)d_in[3];
    const float* b_ih = (const float*)d_in[4];
    const float* b_hh = (const float*)d_in[5];
    const float* W_fc = (const float*)d_in[6];
    const float* b_fc = (const float*)d_in[7];
    float* out = (float*)d_out;

    const int shbytes = (2 * LL * DEPTH + 4) * RL * (int)sizeof(float);  // 188928
    cudaFuncSetAttribute(charrnn_kernel,
                         cudaFuncAttributeMaxDynamicSharedMemorySize, shbytes);
    charrnn_kernel<<<NBLK, NTHR, shbytes>>>(x, emb, W_ih, W_hh, b_ih, b_hh,
                                            W_fc, b_fc, out);
}

// round 8
// speedup vs baseline: 7.1365x; 1.0577x over previous
#include <cuda_runtime.h>
#include <cstdint>

// CharRNN on GB300 (sm_103a), round 7: GEMM/REC warp specialization.
// 128 blocks x 640 threads (20 warps). Block owns 8 batch rows.
// 20 pipeline stages (2 per layer): stage 2l = GEMM_l (z = Wih.x + bias,
// no serial dep), stage 2l+1 = REC_l (h = tanh(z + Whh.h), the recurrence).
// Warps 0..9 = REC layers 0..9; warps 10..19 = GEMM layers 0..9
// (interleaves roles across SMSPs: each SMSP gets ~2-3 REC + 2-3 GEMM).
// 4 steps/tick, depth-8 rings for h and z, one __syncthreads per tick.
// GEMM_0 gathers embeddings itself (LDG, latency-tolerant) via a tiny
// per-tick smem stage. Lane owns ONE neuron; weights 32 regs per warp role.

#define NBLK  128
#define NTHR  640
#define ROWS  8
#define TT    1024
#define LL    10
#define HID   32
#define VOC   256
#define LST   36
#define RL    (ROWS*LST)
#define DEPTH 8
#define NTICK 275            // last REC9 tick: 4(v-19)+3=1023 -> v=274

typedef unsigned long long ull;

__device__ __forceinline__ void ffma2(ull &d, ull a, ull b) {
    asm("fma.rn.f32x2 %0, %1, %2, %0;" : "+l"(d) : "l"(a), "l"(b));
}
__device__ __forceinline__ float f2red(ull a) {
    float lo, hi;
    asm("mov.b64 {%0, %1}, %2;" : "=f"(lo), "=f"(hi) : "l"(a));
    return lo + hi;
}
__device__ __forceinline__ float tanh_fast(float x) {
    float e = __expf(2.0f * x);
    return 1.0f - __fdividef(2.0f, e + 1.0f);
}

__global__ void __launch_bounds__(NTHR, 1)
charrnn_kernel(const int*   __restrict__ x,
               const float* __restrict__ emb,
               const float* __restrict__ W_ih,
               const float* __restrict__ W_hh,
               const float* __restrict__ b_ih,
               const float* __restrict__ b_hh,
               const float* __restrict__ W_fc,
               const float* __restrict__ b_fc,
               float*       __restrict__ out)
{
    extern __shared__ float smem[];
    float* sh  = smem;                        // h rings [LL][DEPTH][ROWS][LST]
    float* sz  = smem + LL * DEPTH * RL;      // z rings [LL][DEPTH][ROWS][LST]
    float* sxs = sz   + LL * DEPTH * RL;      // GEMM_0 stage [4][ROWS][LST]

    const int tid  = threadIdx.x;
    const int wid  = tid >> 5;
    const int lane = tid & 31;
    const int row0 = blockIdx.x * ROWS;

    // zero h rings (h(-1)=0 read from slot 7 at t=0)
    for (int i = tid; i < LL * DEPTH * RL; i += NTHR) sh[i] = 0.0f;

    const bool isRec = (wid < 10);
    const int  l     = isRec ? wid : (wid - 10);

    // role weights: REC -> Whh row, GEMM -> Wih row (32 regs each)
    ull w[16];
    {
        const float* wsrc = isRec ? (W_hh + (l * HID + lane) * HID)
                                  : (W_ih + (l * HID + lane) * HID);
        const ulonglong2* p = (const ulonglong2*)wsrc;
        #pragma unroll
        for (int q = 0; q < 8; ++q) { ulonglong2 v = p[q]; w[2*q] = v.x; w[2*q+1] = v.y; }
    }
    const float bias = isRec ? 0.0f
                             : (__ldg(&b_ih[l * HID + lane]) + __ldg(&b_hh[l * HID + lane]));

    __syncthreads();

    float*       hown = sh + l * DEPTH * RL;
    const float* hup  = (l > 0) ? (sh + (l - 1) * DEPTH * RL) : sxs;
    float*       zl   = sz + l * DEPTH * RL;

    for (int v = 0; v < NTICK; ++v) {
        if (!isRec) {
            // ================= GEMM stage 2l: z(t) for t = 4(v-2l).. =================
            const int t0 = 4 * (v - 2 * l);
            if (t0 >= 0 && t0 < TT) {
                if (l == 0) {
                    // embedding gather into per-tick stage (own-warp only)
                    #pragma unroll
                    for (int r = 0; r < ROWS; ++r) {
                        const int4 xi = *(const int4*)(x + (row0 + r) * TT + t0);
                        sxs[0 * RL + r * LST + lane] = __ldg(&emb[xi.x * HID + lane]);
                        sxs[1 * RL + r * LST + lane] = __ldg(&emb[xi.y * HID + lane]);
                        sxs[2 * RL + r * LST + lane] = __ldg(&emb[xi.z * HID + lane]);
                        sxs[3 * RL + r * LST + lane] = __ldg(&emb[xi.w * HID + lane]);
                    }
                    __syncwarp();
                }
                #pragma unroll
                for (int st = 0; st < 4; ++st) {
                    const int t = t0 + st;
                    const float* inb = (l == 0) ? (sxs + st * RL)
                                                : (hup + (t & (DEPTH-1)) * RL);
                    float* zo = zl + (t & (DEPTH-1)) * RL;

                    #pragma unroll
                    for (int r = 0; r < ROWS; r += 2) {
                        ull a0 = 0ull, a1 = 0ull;
                        #pragma unroll
                        for (int q = 0; q < 8; ++q) {
                            ulonglong2 v0 = *(const ulonglong2*)(inb + (r+0) * LST + q * 4);
                            ulonglong2 v1 = *(const ulonglong2*)(inb + (r+1) * LST + q * 4);
                            ffma2(a0, w[2*q], v0.x); ffma2(a0, w[2*q+1], v0.y);
                            ffma2(a1, w[2*q], v1.x); ffma2(a1, w[2*q+1], v1.y);
                        }
                        zo[(r+0) * LST + lane] = f2red(a0) + bias;
                        zo[(r+1) * LST + lane] = f2red(a1) + bias;
                    }
                }
            }
        } else {
            // ================= REC stage 2l+1: h(t) for t = 4(v-2l-1).. =================
            const int t0 = 4 * (v - 2 * l - 1);
            if (t0 >= 0 && t0 < TT) {
                #pragma unroll
                for (int st = 0; st < 4; ++st) {
                    const int t = t0 + st;
                    const float* hb   = hown + ((t - 1) & (DEPTH-1)) * RL;
                    const float* zrow = zl   + (t & (DEPTH-1)) * RL;
                    float*       ob   = hown + (t & (DEPTH-1)) * RL;

                    // z values first (independent of h)
                    float zv[ROWS];
                    #pragma unroll
                    for (int r = 0; r < ROWS; ++r) zv[r] = zrow[r * LST + lane];

                    ull a[ROWS];
                    #pragma unroll
                    for (int r = 0; r < ROWS; ++r) a[r] = 0ull;
                    #pragma unroll
                    for (int r = 0; r < ROWS; r += 2) {
                        #pragma unroll
                        for (int q = 0; q < 8; ++q) {
                            ulonglong2 v0 = *(const ulonglong2*)(hb + (r+0) * LST + q * 4);
                            ulonglong2 v1 = *(const ulonglong2*)(hb + (r+1) * LST + q * 4);
                            ffma2(a[r+0], w[2*q], v0.x); ffma2(a[r+0], w[2*q+1], v0.y);
                            ffma2(a[r+1], w[2*q], v1.x); ffma2(a[r+1], w[2*q+1], v1.y);
                        }
                    }
                    #pragma unroll
                    for (int r = 0; r < ROWS; ++r)
                        ob[r * LST + lane] = tanh_fast(f2red(a[r]) + zv[r]);
                    __syncwarp();   // own next step reads all lanes' h
                }
            }
        }
        __syncthreads();   // tick rendezvous: publishes h and z cross-warp
    }

    // ---- final FC: out = h9(1023) @ W_fc^T + b_fc ; slot 1023&7 = 7 ----
    const float* h9 = sh + ((LL - 1) * DEPTH + 7) * RL;
    for (int i = tid; i < ROWS * VOC; i += NTHR) {
        const int r  = i >> 8;
        const int vv = i & (VOC - 1);
        const float4* wfc = (const float4*)(W_fc + vv * HID);
        const float*  hr  = h9 + r * LST;
        float sum = __ldg(&b_fc[vv]);
        #pragma unroll
        for (int q = 0; q < 8; ++q) {
            float4 aw = wfc[q];
            sum += aw.x * hr[q*4+0] + aw.y * hr[q*4+1] + aw.z * hr[q*4+2] + aw.w * hr[q*4+3];
        }
        out[(row0 + r) * VOC + vv] = sum;
    }
}

extern "C" void kernel_launch(void* const* d_in, const int* in_sizes, int n_in,
                              void* d_out, int out_size)
{
    const int*   x    = (const int*)  d_in[0];
    const float* emb  = (const float*)d_in[1];
    const float* W_ih = (const float*)d_in[2];
    const float* W_hh = (const float*)d_in[3];
    const float* b_ih = (const float*)d_in[4];
    const float* b_hh = (const float*)d_in[5];
    const float* W_fc = (const float*)d_in[6];
    const float* b_fc = (const float*)d_in[7];
    float* out = (float*)d_out;

    const int shbytes = (2 * LL * DEPTH + 4) * RL * (int)sizeof(float);  // 188928
    cudaFuncSetAttribute(charrnn_kernel,
                         cudaFuncAttributeMaxDynamicSharedMemorySize, shbytes);
    charrnn_kernel<<<NBLK, NTHR, shbytes>>>(x, emb, W_ih, W_hh, b_ih, b_hh,
                                            W_fc, b_fc, out);
}

// round 9
// speedup vs baseline: 8.2184x; 1.1516x over previous
#include <cuda_runtime.h>
#include <cstdint>

// CharRNN on GB300 (sm_103a), round 8: GEMM/REC specialization (R7) +
// 2-neuron-per-lane REC layout (halves REC LDS, shortens the serial chain).
// 128 blocks x 640 threads (20 warps), 8 batch rows per block.
// Stages: 2l = GEMM_l (z = Wih.x + bias, streaming), 2l+1 = REC_l
// (h = tanh(z + Whh.h)). Warps 0..9 = REC, 10..19 = GEMM. 4 steps/tick,
// depth-8 h/z rings, ONE __syncthreads per tick. GEMM_0 gathers embeddings.
// REC lane owns neurons (n, n+16) for its 4-row half -> each LDS.128 feeds
// 4 ffma2. GEMM lane owns one neuron for all 8 rows (pure fodder).

#define NBLK  128
#define NTHR  640
#define ROWS  8
#define TT    1024
#define LL    10
#define HID   32
#define VOC   256
#define LST   36
#define RL    (ROWS*LST)
#define DEPTH 8
#define NTICK 275

typedef unsigned long long ull;

__device__ __forceinline__ void ffma2(ull &d, ull a, ull b) {
    asm("fma.rn.f32x2 %0, %1, %2, %0;" : "+l"(d) : "l"(a), "l"(b));
}
__device__ __forceinline__ float f2red(ull a) {
    float lo, hi;
    asm("mov.b64 {%0, %1}, %2;" : "=f"(lo), "=f"(hi) : "l"(a));
    return lo + hi;
}
__device__ __forceinline__ float tanh_fast(float x) {
    float e = __expf(2.0f * x);
    return 1.0f - __fdividef(2.0f, e + 1.0f);
}

__global__ void __launch_bounds__(NTHR, 1)
charrnn_kernel(const int*   __restrict__ x,
               const float* __restrict__ emb,
               const float* __restrict__ W_ih,
               const float* __restrict__ W_hh,
               const float* __restrict__ b_ih,
               const float* __restrict__ b_hh,
               const float* __restrict__ W_fc,
               const float* __restrict__ b_fc,
               float*       __restrict__ out)
{
    extern __shared__ float smem[];
    float* sh  = smem;                        // h rings [LL][DEPTH][ROWS][LST]
    float* sz  = smem + LL * DEPTH * RL;      // z rings [LL][DEPTH][ROWS][LST]
    float* sxs = sz   + LL * DEPTH * RL;      // GEMM_0 stage [4][ROWS][LST]

    const int tid  = threadIdx.x;
    const int wid  = tid >> 5;
    const int lane = tid & 31;
    const int row0 = blockIdx.x * ROWS;

    for (int i = tid; i < LL * DEPTH * RL; i += NTHR) sh[i] = 0.0f;

    const bool isRec = (wid < 10);
    const int  l     = isRec ? wid : (wid - 10);

    float*       hown = sh + l * DEPTH * RL;
    const float* hup  = (l > 0) ? (sh + (l - 1) * DEPTH * RL) : sxs;
    float*       zl   = sz + l * DEPTH * RL;

    if (isRec) {
        // ======================= REC warp: 2 neurons/lane =======================
        const int half = lane >> 4;       // row half (0: rows 0-3, 1: rows 4-7)
        const int rb   = half * 4;
        const int n0   = lane & 15;
        const int n1   = n0 + 16;

        ull whh0[16], whh1[16];
        {
            const ulonglong2* p = (const ulonglong2*)(W_hh + (l * HID + n0) * HID);
            #pragma unroll
            for (int q = 0; q < 8; ++q) { ulonglong2 v = p[q]; whh0[2*q] = v.x; whh0[2*q+1] = v.y; }
            p = (const ulonglong2*)(W_hh + (l * HID + n1) * HID);
            #pragma unroll
            for (int q = 0; q < 8; ++q) { ulonglong2 v = p[q]; whh1[2*q] = v.x; whh1[2*q+1] = v.y; }
        }
        __syncthreads();

        for (int v = 0; v < NTICK; ++v) {
            const int t0 = 4 * (v - 2 * l - 1);
            if (t0 >= 0 && t0 < TT) {
                #pragma unroll
                for (int st = 0; st < 4; ++st) {
                    const int t = t0 + st;
                    const float* hb   = hown + ((t - 1) & (DEPTH-1)) * RL;
                    const float* zrow = zl   + (t & (DEPTH-1)) * RL;
                    float*       ob   = hown + (t & (DEPTH-1)) * RL;

                    #pragma unroll
                    for (int g = 0; g < 2; ++g) {
                        const int rA = rb + 2*g;
                        const int rB = rA + 1;
                        ull a00 = 0ull, a01 = 0ull, a10 = 0ull, a11 = 0ull;
                        #pragma unroll
                        for (int q = 0; q < 8; ++q) {
                            ulonglong2 vA = *(const ulonglong2*)(hb + rA * LST + q * 4);
                            ulonglong2 vB = *(const ulonglong2*)(hb + rB * LST + q * 4);
                            ffma2(a00, whh0[2*q], vA.x); ffma2(a00, whh0[2*q+1], vA.y);
                            ffma2(a01, whh1[2*q], vA.x); ffma2(a01, whh1[2*q+1], vA.y);
                            ffma2(a10, whh0[2*q], vB.x); ffma2(a10, whh0[2*q+1], vB.y);
                            ffma2(a11, whh1[2*q], vB.x); ffma2(a11, whh1[2*q+1], vB.y);
                        }
                        ob[rA * LST + n0] = tanh_fast(f2red(a00) + zrow[rA * LST + n0]);
                        ob[rA * LST + n1] = tanh_fast(f2red(a01) + zrow[rA * LST + n1]);
                        ob[rB * LST + n0] = tanh_fast(f2red(a10) + zrow[rB * LST + n0]);
                        ob[rB * LST + n1] = tanh_fast(f2red(a11) + zrow[rB * LST + n1]);
                    }
                    __syncwarp();
                }
            }
            __syncthreads();
        }
    } else {
        // ======================= GEMM warp: 1 neuron/lane =======================
        ull wih[16];
        {
            const ulonglong2* p = (const ulonglong2*)(W_ih + (l * HID + lane) * HID);
            #pragma unroll
            for (int q = 0; q < 8; ++q) { ulonglong2 v = p[q]; wih[2*q] = v.x; wih[2*q+1] = v.y; }
        }
        const float bias = __ldg(&b_ih[l * HID + lane]) + __ldg(&b_hh[l * HID + lane]);
        __syncthreads();

        for (int v = 0; v < NTICK; ++v) {
            const int t0 = 4 * (v - 2 * l);
            if (t0 >= 0 && t0 < TT) {
                if (l == 0) {
                    #pragma unroll
                    for (int r = 0; r < ROWS; ++r) {
                        const int4 xi = *(const int4*)(x + (row0 + r) * TT + t0);
                        sxs[0 * RL + r * LST + lane] = __ldg(&emb[xi.x * HID + lane]);
                        sxs[1 * RL + r * LST + lane] = __ldg(&emb[xi.y * HID + lane]);
                        sxs[2 * RL + r * LST + lane] = __ldg(&emb[xi.z * HID + lane]);
                        sxs[3 * RL + r * LST + lane] = __ldg(&emb[xi.w * HID + lane]);
                    }
                    __syncwarp();
                }
                #pragma unroll
                for (int st = 0; st < 4; ++st) {
                    const int t = t0 + st;
                    const float* inb = (l == 0) ? (sxs + st * RL)
                                                : (hup + (t & (DEPTH-1)) * RL);
                    float* zo = zl + (t & (DEPTH-1)) * RL;

                    #pragma unroll
                    for (int r = 0; r < ROWS; r += 2) {
                        ull a0 = 0ull, a1 = 0ull;
                        #pragma unroll
                        for (int q = 0; q < 8; ++q) {
                            ulonglong2 v0 = *(const ulonglong2*)(inb + (r+0) * LST + q * 4);
                            ulonglong2 v1 = *(const ulonglong2*)(inb + (r+1) * LST + q * 4);
                            ffma2(a0, wih[2*q], v0.x); ffma2(a0, wih[2*q+1], v0.y);
                            ffma2(a1, wih[2*q], v1.x); ffma2(a1, wih[2*q+1], v1.y);
                        }
                        zo[(r+0) * LST + lane] = f2red(a0) + bias;
                        zo[(r+1) * LST + lane] = f2red(a1) + bias;
                    }
                }
            }
            __syncthreads();
        }
    }

    __syncthreads();

    // ---- final FC: out = h9(1023) @ W_fc^T + b_fc ; slot 1023&7 = 7 ----
    const float* h9 = sh + ((LL - 1) * DEPTH + 7) * RL;
    for (int i = tid; i < ROWS * VOC; i += NTHR) {
        const int r  = i >> 8;
        const int vv = i & (VOC - 1);
        const float4* wfc = (const float4*)(W_fc + vv * HID);
        const float*  hr  = h9 + r * LST;
        float sum = __ldg(&b_fc[vv]);
        #pragma unroll
        for (int q = 0; q < 8; ++q) {
            float4 aw = wfc[q];
            sum += aw.x * hr[q*4+0] + aw.y * hr[q*4+1] + aw.z * hr[q*4+2] + aw.w * hr[q*4+3];
        }
        out[(row0 + r) * VOC + vv] = sum;
    }
}

extern "C" void kernel_launch(void* const* d_in, const int* in_sizes, int n_in,
                              void* d_out, int out_size)
{
    const int*   x    = (const int*)  d_in[0];
    const float* emb  = (const float*)d_in[1];
    const float* W_ih = (const float*)d_in[2];
    const float* W_hh = (const float*)d_in[3];
    const float* b_ih = (const float*)d_in[4];
    const float* b_hh = (const float*)d_in[5];
    const float* W_fc = (const float*)d_in[6];
    const float* b_fc = (const float*)d_in[7];
    float* out = (float*)d_out;

    const int shbytes = (2 * LL * DEPTH + 4) * RL * (int)sizeof(float);  // 188928
    cudaFuncSetAttribute(charrnn_kernel,
                         cudaFuncAttributeMaxDynamicSharedMemorySize, shbytes);
    charrnn_kernel<<<NBLK, NTHR, shbytes>>>(x, emb, W_ih, W_hh, b_ih, b_hh,
                                            W_fc, b_fc, out);
}

// round 10
// speedup vs baseline: 8.6491x; 1.0524x over previous
#include <cuda_runtime.h>
#include <cstdint>

// CharRNN on GB300 (sm_103a), round 9: R8 + 2-neuron/lane GEMM warps.
// 128 blocks x 640 threads (20 warps), 8 batch rows per block.
// Stages: 2l = GEMM_l (z = Wih.x + bias, streaming), 2l+1 = REC_l
// (h = tanh(z + Whh.h)). Warps 0..9 = REC, 10..19 = GEMM. 4 steps/tick,
// depth-8 h/z rings, ONE __syncthreads per tick. GEMM_0 gathers embeddings.
// BOTH roles: lane owns neurons (n, n+16) for its 4-row half -> every
// LDS.128 feeds 4 packed fma.rn.f32x2.

#define NBLK  128
#define NTHR  640
#define ROWS  8
#define TT    1024
#define LL    10
#define HID   32
#define VOC   256
#define LST   36
#define RL    (ROWS*LST)
#define DEPTH 8
#define NTICK 275

typedef unsigned long long ull;

__device__ __forceinline__ void ffma2(ull &d, ull a, ull b) {
    asm("fma.rn.f32x2 %0, %1, %2, %0;" : "+l"(d) : "l"(a), "l"(b));
}
__device__ __forceinline__ float f2red(ull a) {
    float lo, hi;
    asm("mov.b64 {%0, %1}, %2;" : "=f"(lo), "=f"(hi) : "l"(a));
    return lo + hi;
}
__device__ __forceinline__ float tanh_fast(float x) {
    float e = __expf(2.0f * x);
    return 1.0f - __fdividef(2.0f, e + 1.0f);
}

__global__ void __launch_bounds__(NTHR, 1)
charrnn_kernel(const int*   __restrict__ x,
               const float* __restrict__ emb,
               const float* __restrict__ W_ih,
               const float* __restrict__ W_hh,
               const float* __restrict__ b_ih,
               const float* __restrict__ b_hh,
               const float* __restrict__ W_fc,
               const float* __restrict__ b_fc,
               float*       __restrict__ out)
{
    extern __shared__ float smem[];
    float* sh  = smem;                        // h rings [LL][DEPTH][ROWS][LST]
    float* sz  = smem + LL * DEPTH * RL;      // z rings [LL][DEPTH][ROWS][LST]
    float* sxs = sz   + LL * DEPTH * RL;      // GEMM_0 stage [4][ROWS][LST]

    const int tid  = threadIdx.x;
    const int wid  = tid >> 5;
    const int lane = tid & 31;
    const int row0 = blockIdx.x * ROWS;

    for (int i = tid; i < LL * DEPTH * RL; i += NTHR) sh[i] = 0.0f;

    const bool isRec = (wid < 10);
    const int  l     = isRec ? wid : (wid - 10);

    float*       hown = sh + l * DEPTH * RL;
    const float* hup  = (l > 0) ? (sh + (l - 1) * DEPTH * RL) : sxs;
    float*       zl   = sz + l * DEPTH * RL;

    const int half = lane >> 4;       // row half (0: rows 0-3, 1: rows 4-7)
    const int rb   = half * 4;
    const int n0   = lane & 15;       // owned neurons n0, n0+16
    const int n1   = n0 + 16;

    if (isRec) {
        // ======================= REC warp: h = tanh(z + Whh.h) =======================
        ull whh0[16], whh1[16];
        {
            const ulonglong2* p = (const ulonglong2*)(W_hh + (l * HID + n0) * HID);
            #pragma unroll
            for (int q = 0; q < 8; ++q) { ulonglong2 v = p[q]; whh0[2*q] = v.x; whh0[2*q+1] = v.y; }
            p = (const ulonglong2*)(W_hh + (l * HID + n1) * HID);
            #pragma unroll
            for (int q = 0; q < 8; ++q) { ulonglong2 v = p[q]; whh1[2*q] = v.x; whh1[2*q+1] = v.y; }
        }
        __syncthreads();

        for (int v = 0; v < NTICK; ++v) {
            const int t0 = 4 * (v - 2 * l - 1);
            if (t0 >= 0 && t0 < TT) {
                #pragma unroll
                for (int st = 0; st < 4; ++st) {
                    const int t = t0 + st;
                    const float* hb   = hown + ((t - 1) & (DEPTH-1)) * RL;
                    const float* zrow = zl   + (t & (DEPTH-1)) * RL;
                    float*       ob   = hown + (t & (DEPTH-1)) * RL;

                    #pragma unroll
                    for (int g = 0; g < 2; ++g) {
                        const int rA = rb + 2*g;
                        const int rB = rA + 1;
                        ull a00 = 0ull, a01 = 0ull, a10 = 0ull, a11 = 0ull;
                        #pragma unroll
                        for (int q = 0; q < 8; ++q) {
                            ulonglong2 vA = *(const ulonglong2*)(hb + rA * LST + q * 4);
                            ulonglong2 vB = *(const ulonglong2*)(hb + rB * LST + q * 4);
                            ffma2(a00, whh0[2*q], vA.x); ffma2(a00, whh0[2*q+1], vA.y);
                            ffma2(a01, whh1[2*q], vA.x); ffma2(a01, whh1[2*q+1], vA.y);
                            ffma2(a10, whh0[2*q], vB.x); ffma2(a10, whh0[2*q+1], vB.y);
                            ffma2(a11, whh1[2*q], vB.x); ffma2(a11, whh1[2*q+1], vB.y);
                        }
                        ob[rA * LST + n0] = tanh_fast(f2red(a00) + zrow[rA * LST + n0]);
                        ob[rA * LST + n1] = tanh_fast(f2red(a01) + zrow[rA * LST + n1]);
                        ob[rB * LST + n0] = tanh_fast(f2red(a10) + zrow[rB * LST + n0]);
                        ob[rB * LST + n1] = tanh_fast(f2red(a11) + zrow[rB * LST + n1]);
                    }
                    __syncwarp();
                }
            }
            __syncthreads();
        }
    } else {
        // ======================= GEMM warp: z = Wih.x + bias =======================
        ull wih0[16], wih1[16];
        {
            const ulonglong2* p = (const ulonglong2*)(W_ih + (l * HID + n0) * HID);
            #pragma unroll
            for (int q = 0; q < 8; ++q) { ulonglong2 v = p[q]; wih0[2*q] = v.x; wih0[2*q+1] = v.y; }
            p = (const ulonglong2*)(W_ih + (l * HID + n1) * HID);
            #pragma unroll
            for (int q = 0; q < 8; ++q) { ulonglong2 v = p[q]; wih1[2*q] = v.x; wih1[2*q+1] = v.y; }
        }
        const float bias0 = __ldg(&b_ih[l * HID + n0]) + __ldg(&b_hh[l * HID + n0]);
        const float bias1 = __ldg(&b_ih[l * HID + n1]) + __ldg(&b_hh[l * HID + n1]);
        __syncthreads();

        for (int v = 0; v < NTICK; ++v) {
            const int t0 = 4 * (v - 2 * l);
            if (t0 >= 0 && t0 < TT) {
                if (l == 0) {
                    #pragma unroll
                    for (int r = 0; r < ROWS; ++r) {
                        const int4 xi = *(const int4*)(x + (row0 + r) * TT + t0);
                        sxs[0 * RL + r * LST + lane] = __ldg(&emb[xi.x * HID + lane]);
                        sxs[1 * RL + r * LST + lane] = __ldg(&emb[xi.y * HID + lane]);
                        sxs[2 * RL + r * LST + lane] = __ldg(&emb[xi.z * HID + lane]);
                        sxs[3 * RL + r * LST + lane] = __ldg(&emb[xi.w * HID + lane]);
                    }
                    __syncwarp();
                }
                #pragma unroll
                for (int st = 0; st < 4; ++st) {
                    const int t = t0 + st;
                    const float* inb = (l == 0) ? (sxs + st * RL)
                                                : (hup + (t & (DEPTH-1)) * RL);
                    float* zo = zl + (t & (DEPTH-1)) * RL;

                    #pragma unroll
                    for (int g = 0; g < 2; ++g) {
                        const int rA = rb + 2*g;
                        const int rB = rA + 1;
                        ull a00 = 0ull, a01 = 0ull, a10 = 0ull, a11 = 0ull;
                        #pragma unroll
                        for (int q = 0; q < 8; ++q) {
                            ulonglong2 vA = *(const ulonglong2*)(inb + rA * LST + q * 4);
                            ulonglong2 vB = *(const ulonglong2*)(inb + rB * LST + q * 4);
                            ffma2(a00, wih0[2*q], vA.x); ffma2(a00, wih0[2*q+1], vA.y);
                            ffma2(a01, wih1[2*q], vA.x); ffma2(a01, wih1[2*q+1], vA.y);
                            ffma2(a10, wih0[2*q], vB.x); ffma2(a10, wih0[2*q+1], vB.y);
                            ffma2(a11, wih1[2*q], vB.x); ffma2(a11, wih1[2*q+1], vB.y);
                        }
                        zo[rA * LST + n0] = f2red(a00) + bias0;
                        zo[rA * LST + n1] = f2red(a01) + bias1;
                        zo[rB * LST + n0] = f2red(a10) + bias0;
                        zo[rB * LST + n1] = f2red(a11) + bias1;
                    }
                }
            }
            __syncthreads();
        }
    }

    __syncthreads();

    // ---- final FC: out = h9(1023) @ W_fc^T + b_fc ; slot 1023&7 = 7 ----
    const float* h9 = sh + ((LL - 1) * DEPTH + 7) * RL;
    for (int i = tid; i < ROWS * VOC; i += NTHR) {
        const int r  = i >> 8;
        const int vv = i & (VOC - 1);
        const float4* wfc = (const float4*)(W_fc + vv * HID);
        const float*  hr  = h9 + r * LST;
        float sum = __ldg(&b_fc[vv]);
        #pragma unroll
        for (int q = 0; q < 8; ++q) {
            float4 aw = wfc[q];
            sum += aw.x * hr[q*4+0] + aw.y * hr[q*4+1] + aw.z * hr[q*4+2] + aw.w * hr[q*4+3];
        }
        out[(row0 + r) * VOC + vv] = sum;
    }
}

extern "C" void kernel_launch(void* const* d_in, const int* in_sizes, int n_in,
                              void* d_out, int out_size)
{
    const int*   x    = (const int*)  d_in[0];
    const float* emb  = (const float*)d_in[1];
    const float* W_ih = (const float*)d_in[2];
    const float* W_hh = (const float*)d_in[3];
    const float* b_ih = (const float*)d_in[4];
    const float* b_hh = (const float*)d_in[5];
    const float* W_fc = (const float*)d_in[6];
    const float* b_fc = (const float*)d_in[7];
    float* out = (float*)d_out;

    const int shbytes = (2 * LL * DEPTH + 4) * RL * (int)sizeof(float);  // 188928
    cudaFuncSetAttribute(charrnn_kernel,
                         cudaFuncAttributeMaxDynamicSharedMemorySize, shbytes);
    charrnn_kernel<<<NBLK, NTHR, shbytes>>>(x, emb, W_ih, W_hh, b_ih, b_hh,
                                            W_fc, b_fc, out);
}